// round 4
// baseline (speedup 1.0000x reference)
#include <cuda_runtime.h>
#include <cuda_bf16.h>
#include <stdint.h>

// Problem constants (B=4, S=4096, HID=1024, H=16, D=64)
#define GM 16384            // B*S
#define GN 1024             // HID
#define GK 1024             // HID
#define NPOS 16384          // B*S  (attention positions)
#define ATT_ELEMS (NPOS * 256)        // B*S*16*16 = 4194304
#define MAIN_OUT_ELEMS (GM * GN)      // 16777216

// Scratch (device globals — no allocations allowed). Referenced directly
// from device code. 16B-aligned for float4 access.
__device__ __align__(16) float g_Q[GM * GN];
__device__ __align__(16) float g_K[GM * GN];
__device__ __align__(16) float g_V[GM * GN];
__device__ __align__(16) float g_X[GM * GN];      // attn output, (B,H,S,D) layout

// ---------------------------------------------------------------------------
// bf16x3 split helpers
// ---------------------------------------------------------------------------
__device__ __forceinline__ void bsplit2(float x, float y, uint32_t& h, uint32_t& l) {
    __nv_bfloat16 hx = __float2bfloat16_rn(x);
    __nv_bfloat16 hy = __float2bfloat16_rn(y);
    float rx = x - __bfloat162float(hx);
    float ry = y - __bfloat162float(hy);
    __nv_bfloat162 hh = __halves2bfloat162(hx, hy);
    __nv_bfloat162 ll = __halves2bfloat162(__float2bfloat16_rn(rx), __float2bfloat16_rn(ry));
    h = *reinterpret_cast<uint32_t*>(&hh);
    l = *reinterpret_cast<uint32_t*>(&ll);
}

__device__ __forceinline__ void mma16816(float* c, const uint32_t* a, uint32_t b0, uint32_t b1) {
    asm volatile(
        "mma.sync.aligned.m16n8k16.row.col.f32.bf16.bf16.f32 "
        "{%0,%1,%2,%3}, {%4,%5,%6,%7}, {%8,%9}, {%0,%1,%2,%3};"
        : "+f"(c[0]), "+f"(c[1]), "+f"(c[2]), "+f"(c[3])
        : "r"(a[0]), "r"(a[1]), "r"(a[2]), "r"(a[3]), "r"(b0), "r"(b1));
}

// ---------------------------------------------------------------------------
// GEMM: C[M,N] = A[M,K] @ W[K,N] + bias[N]   (fp32 in/out, bf16x3 internally)
// CTA tile 128x128, BK=32, 8 warps (2x4), warp tile 64x32.
// a_tag / c_tag select device-global scratch when the pointer param is null:
//   tag 1 -> g_Q, 2 -> g_K, 3 -> g_V, 4 -> g_X
// ---------------------------------------------------------------------------
#define SMSTRIDE 40  // bf16 elements per smem row (padding for conflict-free frags)

__device__ __forceinline__ float* scratch_ptr(int tag) {
    switch (tag) {
        case 1: return g_Q;
        case 2: return g_K;
        case 3: return g_V;
        default: return g_X;
    }
}

__global__ __launch_bounds__(256, 2) void gemm_bias_kernel(
    const float* Ain, int a_tag, const float* __restrict__ W,
    const float* __restrict__ bias, float* Cout, int c_tag)
{
    const float* A = Ain ? Ain : scratch_ptr(a_tag);
    float* C = Cout ? Cout : scratch_ptr(c_tag);

    __shared__ __align__(16) __nv_bfloat16 Ah[128 * SMSTRIDE];
    __shared__ __align__(16) __nv_bfloat16 Al[128 * SMSTRIDE];
    __shared__ __align__(16) __nv_bfloat16 Bh[128 * SMSTRIDE];
    __shared__ __align__(16) __nv_bfloat16 Bl[128 * SMSTRIDE];

    const int tid  = threadIdx.x;
    const int warp = tid >> 5;
    const int lane = tid & 31;
    const int gid  = lane >> 2;   // 0..7
    const int tig  = lane & 3;    // 0..3
    const int wm = (warp >> 2) * 64;  // 0 or 64
    const int wn = (warp & 3) * 32;   // 0,32,64,96
    const int bm = blockIdx.y * 128;
    const int bn = blockIdx.x * 128;

    float acc[4][4][4];
    #pragma unroll
    for (int a = 0; a < 4; a++)
        #pragma unroll
        for (int b = 0; b < 4; b++)
            #pragma unroll
            for (int c = 0; c < 4; c++) acc[a][b][c] = 0.f;

    for (int kt = 0; kt < GK; kt += 32) {
        // ---- load A tile 128x32 (fp32), split to bf16 hi/lo ----
        #pragma unroll
        for (int i = 0; i < 4; i++) {
            int idx = tid + i * 256;        // 0..1023
            int r   = idx >> 3;             // row 0..127
            int c4  = (idx & 7) * 4;        // col 0..28 step 4
            float4 v = *reinterpret_cast<const float4*>(A + (size_t)(bm + r) * GK + kt + c4);
            uint32_t h01, l01, h23, l23;
            bsplit2(v.x, v.y, h01, l01);
            bsplit2(v.z, v.w, h23, l23);
            *reinterpret_cast<uint32_t*>(&Ah[r * SMSTRIDE + c4])     = h01;
            *reinterpret_cast<uint32_t*>(&Ah[r * SMSTRIDE + c4 + 2]) = h23;
            *reinterpret_cast<uint32_t*>(&Al[r * SMSTRIDE + c4])     = l01;
            *reinterpret_cast<uint32_t*>(&Al[r * SMSTRIDE + c4 + 2]) = l23;
        }
        // ---- load W tile 32x128 (fp32), split + store transposed [n][k] ----
        #pragma unroll
        for (int i = 0; i < 4; i++) {
            int idx = tid + i * 256;
            int r   = idx >> 5;             // k row 0..31
            int c4  = (idx & 31) * 4;       // n col 0..124 step 4
            float4 v = *reinterpret_cast<const float4*>(W + (size_t)(kt + r) * GN + bn + c4);
            float xs[4] = {v.x, v.y, v.z, v.w};
            #pragma unroll
            for (int j = 0; j < 4; j++) {
                __nv_bfloat16 h = __float2bfloat16_rn(xs[j]);
                __nv_bfloat16 l = __float2bfloat16_rn(xs[j] - __bfloat162float(h));
                Bh[(c4 + j) * SMSTRIDE + r] = h;
                Bl[(c4 + j) * SMSTRIDE + r] = l;
            }
        }
        __syncthreads();

        #pragma unroll
        for (int ks = 0; ks < 2; ks++) {
            const int kb = ks * 16 + tig * 2;
            uint32_t ah[4][4], al[4][4];
            #pragma unroll
            for (int mi = 0; mi < 4; mi++) {
                int row = wm + mi * 16 + gid;
                ah[mi][0] = *reinterpret_cast<const uint32_t*>(&Ah[row * SMSTRIDE + kb]);
                ah[mi][1] = *reinterpret_cast<const uint32_t*>(&Ah[(row + 8) * SMSTRIDE + kb]);
                ah[mi][2] = *reinterpret_cast<const uint32_t*>(&Ah[row * SMSTRIDE + kb + 8]);
                ah[mi][3] = *reinterpret_cast<const uint32_t*>(&Ah[(row + 8) * SMSTRIDE + kb + 8]);
                al[mi][0] = *reinterpret_cast<const uint32_t*>(&Al[row * SMSTRIDE + kb]);
                al[mi][1] = *reinterpret_cast<const uint32_t*>(&Al[(row + 8) * SMSTRIDE + kb]);
                al[mi][2] = *reinterpret_cast<const uint32_t*>(&Al[row * SMSTRIDE + kb + 8]);
                al[mi][3] = *reinterpret_cast<const uint32_t*>(&Al[(row + 8) * SMSTRIDE + kb + 8]);
            }
            #pragma unroll
            for (int ni = 0; ni < 4; ni++) {
                int nr = wn + ni * 8 + gid;
                uint32_t bh0 = *reinterpret_cast<const uint32_t*>(&Bh[nr * SMSTRIDE + kb]);
                uint32_t bh1 = *reinterpret_cast<const uint32_t*>(&Bh[nr * SMSTRIDE + kb + 8]);
                uint32_t bl0 = *reinterpret_cast<const uint32_t*>(&Bl[nr * SMSTRIDE + kb]);
                uint32_t bl1 = *reinterpret_cast<const uint32_t*>(&Bl[nr * SMSTRIDE + kb + 8]);
                #pragma unroll
                for (int mi = 0; mi < 4; mi++) {
                    mma16816(acc[mi][ni], ah[mi], bh0, bh1);   // hi*hi
                    mma16816(acc[mi][ni], ah[mi], bl0, bl1);   // hi*lo
                    mma16816(acc[mi][ni], al[mi], bh0, bh1);   // lo*hi
                }
            }
        }
        __syncthreads();
    }

    // epilogue: bias + store
    #pragma unroll
    for (int mi = 0; mi < 4; mi++) {
        int row = bm + wm + mi * 16 + gid;
        #pragma unroll
        for (int ni = 0; ni < 4; ni++) {
            int col = bn + wn + ni * 8 + tig * 2;
            float b0 = bias[col], b1 = bias[col + 1];
            float2 r01 = make_float2(acc[mi][ni][0] + b0, acc[mi][ni][1] + b1);
            float2 r23 = make_float2(acc[mi][ni][2] + b0, acc[mi][ni][3] + b1);
            *reinterpret_cast<float2*>(&C[(size_t)row * GN + col])       = r01;
            *reinterpret_cast<float2*>(&C[(size_t)(row + 8) * GN + col]) = r23;
        }
    }
}

// ---------------------------------------------------------------------------
// Per-position attention: one CTA per (b,s) — 16384 CTAs. 16x16 head scores.
// Reads g_Q/g_K/g_V directly, writes g_X ((B,H,S,D) layout).
// Writes attention probabilities to AT only if AT != nullptr.
// ---------------------------------------------------------------------------
__global__ __launch_bounds__(256) void attn_kernel(
    const float* __restrict__ SW, float* AT)
{
    const int p = blockIdx.x;       // 0..16383
    const int b = p >> 12;          // p / 4096
    const int s = p & 4095;
    const int tid = threadIdx.x;

    __shared__ __align__(16) float qs[16][65];
    __shared__ __align__(16) float ks_[16][65];
    __shared__ __align__(16) float vs[16][64];
    __shared__ float qn2[16], kn2[16];
    __shared__ float att[16][16];

    const size_t base = (size_t)p * 1024;

    // load q,k,v tiles (each 16x64 fp32)
    {
        int e = tid * 4;
        int r = e >> 6, d = e & 63;
        float4 qv = *reinterpret_cast<const float4*>(g_Q + base + e);
        float4 kv = *reinterpret_cast<const float4*>(g_K + base + e);
        float4 vv = *reinterpret_cast<const float4*>(g_V + base + e);
        qs[r][d] = qv.x; qs[r][d + 1] = qv.y; qs[r][d + 2] = qv.z; qs[r][d + 3] = qv.w;
        ks_[r][d] = kv.x; ks_[r][d + 1] = kv.y; ks_[r][d + 2] = kv.z; ks_[r][d + 3] = kv.w;
        *reinterpret_cast<float4*>(&vs[r][d]) = vv;
    }
    // score mixing weights = softmax(score_weights)
    float w0, w1, w2;
    {
        float s0 = SW[0], s1 = SW[1], s2 = SW[2];
        float mx = fmaxf(s0, fmaxf(s1, s2));
        float e0 = expf(s0 - mx), e1 = expf(s1 - mx), e2 = expf(s2 - mx);
        float inv = 1.f / (e0 + e1 + e2);
        w0 = e0 * inv; w1 = e1 * inv; w2 = e2 * inv;
    }
    __syncthreads();

    // squared norms of q and k rows
    if (tid < 32) {
        int r = tid & 15;
        const float* src = (tid < 16) ? qs[r] : ks_[r];
        float ssum = 0.f;
        #pragma unroll 8
        for (int d = 0; d < 64; d++) ssum += src[d] * src[d];
        if (tid < 16) qn2[r] = ssum; else kn2[r] = ssum;
    }
    __syncthreads();

    // scores + softmax over j (16-lane shfl segments)
    {
        int i = tid >> 4, j = tid & 15;
        float qk = 0.f;
        #pragma unroll 8
        for (int d = 0; d < 64; d++) qk += qs[i][d] * ks_[j][d];
        float sq = qn2[i], sk = kn2[j];
        float dots  = qk * 0.125f;                               // / sqrt(64)
        float denom = fmaxf(sqrtf(sq) * sqrtf(sk), 1e-8f);
        float cosv  = qk / denom;
        float d2    = fmaxf(sq + sk - 2.f * qk, 0.f);
        float dist  = -sqrtf(d2);
        float sc = w0 * dots + w1 * cosv + w2 * dist;

        float mx = sc;
        #pragma unroll
        for (int o = 8; o; o >>= 1) mx = fmaxf(mx, __shfl_xor_sync(0xffffffffu, mx, o, 16));
        float e = expf(sc - mx);
        float sm = e;
        #pragma unroll
        for (int o = 8; o; o >>= 1) sm += __shfl_xor_sync(0xffffffffu, sm, o, 16);
        float a = e / sm;
        att[i][j] = a;
        if (AT) AT[(size_t)p * 256 + tid] = a;
    }
    __syncthreads();

    // out[i][d] = sum_j att[i][j] * v[j][d]; write to (B,H,S,D) layout
    {
        int i = tid >> 4, d0 = (tid & 15) * 4;
        float4 o = make_float4(0.f, 0.f, 0.f, 0.f);
        #pragma unroll
        for (int j = 0; j < 16; j++) {
            float a = att[i][j];
            float4 v4 = *reinterpret_cast<const float4*>(&vs[j][d0]);
            o.x += a * v4.x; o.y += a * v4.y; o.z += a * v4.z; o.w += a * v4.w;
        }
        size_t xidx = (size_t)b * 4194304 + (size_t)i * 262144 + (size_t)s * 64 + d0;
        *reinterpret_cast<float4*>(&g_X[xidx]) = o;
    }
}

// ---------------------------------------------------------------------------
// kernel_launch
// ---------------------------------------------------------------------------
extern "C" void kernel_launch(void* const* d_in, const int* in_sizes, int n_in,
                              void* d_out, int out_size) {
    (void)in_sizes; (void)n_in;
    const float* query = (const float*)d_in[0];
    const float* key   = (const float*)d_in[1];
    const float* value = (const float*)d_in[2];
    const float* Wq = (const float*)d_in[3];
    const float* bq = (const float*)d_in[4];
    const float* Wk = (const float*)d_in[5];
    const float* bk = (const float*)d_in[6];
    const float* Wv = (const float*)d_in[7];
    const float* bv = (const float*)d_in[8];
    const float* Wo = (const float*)d_in[9];
    const float* bo = (const float*)d_in[10];
    const float* sw = (const float*)d_in[11];
    float* out = (float*)d_out;

    dim3 ggrid(GN / 128, GM / 128);  // (8, 128)
    // Projections: A = harness input, C = device-global scratch (by tag)
    gemm_bias_kernel<<<ggrid, 256>>>(query, 0, Wq, bq, nullptr, 1);
    gemm_bias_kernel<<<ggrid, 256>>>(key,   0, Wk, bk, nullptr, 2);
    gemm_bias_kernel<<<ggrid, 256>>>(value, 0, Wv, bv, nullptr, 3);

    // Attention probabilities go to d_out tail iff the output is the tuple.
    float* attn_dst = (out_size >= MAIN_OUT_ELEMS + ATT_ELEMS) ? (out + MAIN_OUT_ELEMS)
                                                               : nullptr;
    attn_kernel<<<NPOS, 256>>>(sw, attn_dst);

    // Output projection: A = g_X (tag 4), C = d_out
    gemm_bias_kernel<<<ggrid, 256>>>(nullptr, 4, Wo, bo, out, 0);
}

// round 5
// speedup vs baseline: 2.2715x; 2.2715x over previous
#include <cuda_runtime.h>
#include <cuda_bf16.h>
#include <stdint.h>

// Problem constants (B=4, S=4096, HID=1024, H=16, D=64)
#define GM 16384            // B*S
#define GN 1024             // HID
#define GK 1024             // HID
#define NPOS 16384          // B*S  (attention positions)
#define ATT_ELEMS (NPOS * 256)        // 4194304
#define MAIN_OUT_ELEMS (GM * GN)      // 16777216

// Scratch (device globals — no allocations allowed)
__device__ __align__(16) float g_Q[GM * GN];
__device__ __align__(16) float g_K[GM * GN];
__device__ __align__(16) float g_V[GM * GN];
__device__ __align__(16) float g_X[GM * GN];  // attn output, (B,H,S,D) layout

// Pre-split operand buffers (bf16 hi/lo)
__device__ __align__(16) __nv_bfloat16 g_Ah[GM * GK];
__device__ __align__(16) __nv_bfloat16 g_Al[GM * GK];
__device__ __align__(16) __nv_bfloat16 g_Wth[GN * GK];  // W^T [n][k] hi
__device__ __align__(16) __nv_bfloat16 g_Wtl[GN * GK];  // W^T [n][k] lo

// ---------------------------------------------------------------------------
// helpers
// ---------------------------------------------------------------------------
__device__ __forceinline__ void mma16816(float* c, const uint32_t* a, uint32_t b0, uint32_t b1) {
    asm volatile(
        "mma.sync.aligned.m16n8k16.row.col.f32.bf16.bf16.f32 "
        "{%0,%1,%2,%3}, {%4,%5,%6,%7}, {%8,%9}, {%0,%1,%2,%3};"
        : "+f"(c[0]), "+f"(c[1]), "+f"(c[2]), "+f"(c[3])
        : "r"(a[0]), "r"(a[1]), "r"(a[2]), "r"(a[3]), "r"(b0), "r"(b1));
}

__device__ __forceinline__ void ldsm4(uint32_t* r, uint32_t addr) {
    asm volatile("ldmatrix.sync.aligned.m8n8.x4.shared.b16 {%0,%1,%2,%3}, [%4];"
                 : "=r"(r[0]), "=r"(r[1]), "=r"(r[2]), "=r"(r[3]) : "r"(addr));
}

__device__ __forceinline__ void cp16(uint32_t dst, const void* src) {
    asm volatile("cp.async.cg.shared.global [%0], [%1], 16;" :: "r"(dst), "l"(src));
}

// ---------------------------------------------------------------------------
// Split kernels
// ---------------------------------------------------------------------------
// A (or g_X) fp32 [M,K] -> g_Ah/g_Al bf16 same layout. 4 elems/thread.
__global__ __launch_bounds__(256) void split_a_kernel(const float* Ain) {
    const float* A = Ain ? Ain : g_X;
    int idx = blockIdx.x * 256 + threadIdx.x;           // float4 index
    float4 v = reinterpret_cast<const float4*>(A)[idx];
    __nv_bfloat16 h0 = __float2bfloat16_rn(v.x), h1 = __float2bfloat16_rn(v.y);
    __nv_bfloat16 h2 = __float2bfloat16_rn(v.z), h3 = __float2bfloat16_rn(v.w);
    __nv_bfloat16 l0 = __float2bfloat16_rn(v.x - __bfloat162float(h0));
    __nv_bfloat16 l1 = __float2bfloat16_rn(v.y - __bfloat162float(h1));
    __nv_bfloat16 l2 = __float2bfloat16_rn(v.z - __bfloat162float(h2));
    __nv_bfloat16 l3 = __float2bfloat16_rn(v.w - __bfloat162float(h3));
    __nv_bfloat162* Hp = reinterpret_cast<__nv_bfloat162*>(g_Ah);
    __nv_bfloat162* Lp = reinterpret_cast<__nv_bfloat162*>(g_Al);
    Hp[idx * 2]     = __halves2bfloat162(h0, h1);
    Hp[idx * 2 + 1] = __halves2bfloat162(h2, h3);
    Lp[idx * 2]     = __halves2bfloat162(l0, l1);
    Lp[idx * 2 + 1] = __halves2bfloat162(l2, l3);
}

// W fp32 [K,N] -> g_Wth/g_Wtl bf16 [N,K] (transpose + split). 32x32 tiles.
__global__ __launch_bounds__(256) void split_wt_kernel(const float* __restrict__ W) {
    __shared__ float t[32][33];
    int n0 = blockIdx.x * 32, k0 = blockIdx.y * 32;
    int tx = threadIdx.x & 31, ty = threadIdx.x >> 5;   // 32 x 8
    #pragma unroll
    for (int j = 0; j < 4; j++)
        t[ty + 8 * j][tx] = W[(size_t)(k0 + ty + 8 * j) * GN + n0 + tx];
    __syncthreads();
    #pragma unroll
    for (int j = 0; j < 4; j++) {
        int r = ty + 8 * j;
        float v = t[tx][r];                              // = W[k0+tx][n0+r]
        __nv_bfloat16 h = __float2bfloat16_rn(v);
        __nv_bfloat16 l = __float2bfloat16_rn(v - __bfloat162float(h));
        g_Wth[(size_t)(n0 + r) * GK + k0 + tx] = h;
        g_Wtl[(size_t)(n0 + r) * GK + k0 + tx] = l;
    }
}

// ---------------------------------------------------------------------------
// GEMM: C = A @ W + bias, operands pre-split bf16 hi/lo (A [m][k], Wt [n][k]).
// CTA 128x128, BK=32, 8 warps (2x4), warp 64x32. 2-stage cp.async pipeline,
// ldmatrix fragment loads, 3-term compensated MMA.
// smem tile: 128 rows x 80B (32 bf16 padded to 40); conflict-free ldmatrix.
// ---------------------------------------------------------------------------
#define TILE_B   10240              // 128*80
#define STAGE_B  (4 * TILE_B)       // Ah,Al,Bh,Bl
#define GSMEM    (2 * STAGE_B)      // 81920

__device__ __forceinline__ float* out_ptr(int tag) {
    switch (tag) { case 1: return g_Q; case 2: return g_K; default: return g_V; }
}

__global__ __launch_bounds__(256, 2) void gemm_tc_kernel(
    float* Cout, int c_tag, const float* __restrict__ bias)
{
    float* C = Cout ? Cout : out_ptr(c_tag);
    extern __shared__ __align__(16) char sm[];
    const uint32_t smbase = (uint32_t)__cvta_generic_to_shared(sm);

    const int tid  = threadIdx.x;
    const int warp = tid >> 5;
    const int lane = tid & 31;
    const int gid  = lane >> 2;
    const int tig  = lane & 3;
    const int wm = (warp >> 2) * 64;
    const int wn = (warp & 3) * 32;
    const int bm = blockIdx.y * 128;
    const int bn = blockIdx.x * 128;

    // per-thread copy coords: 2 chunks of 16B per tile
    const int crow0 = tid >> 2, cch0 = (tid & 3);
    const int crow1 = (tid + 256) >> 2, cch1 = ((tid + 256) & 3);

    float acc[4][4][4];
    #pragma unroll
    for (int a = 0; a < 4; a++)
        #pragma unroll
        for (int b = 0; b < 4; b++)
            #pragma unroll
            for (int c = 0; c < 4; c++) acc[a][b][c] = 0.f;

    // stage copy: issue 8 cp.asyncs (2 chunks x 4 tiles)
    auto stage_copy = [&](int s, int kt) {
        uint32_t st = smbase + s * STAGE_B;
        const int kof = kt * 32;
        {
            const __nv_bfloat16* ah = g_Ah + (size_t)(bm + crow0) * GK + kof + cch0 * 8;
            const __nv_bfloat16* al = g_Al + (size_t)(bm + crow0) * GK + kof + cch0 * 8;
            const __nv_bfloat16* bh = g_Wth + (size_t)(bn + crow0) * GK + kof + cch0 * 8;
            const __nv_bfloat16* bl = g_Wtl + (size_t)(bn + crow0) * GK + kof + cch0 * 8;
            uint32_t d = st + crow0 * 80 + cch0 * 16;
            cp16(d, ah); cp16(d + TILE_B, al); cp16(d + 2 * TILE_B, bh); cp16(d + 3 * TILE_B, bl);
        }
        {
            const __nv_bfloat16* ah = g_Ah + (size_t)(bm + crow1) * GK + kof + cch1 * 8;
            const __nv_bfloat16* al = g_Al + (size_t)(bm + crow1) * GK + kof + cch1 * 8;
            const __nv_bfloat16* bh = g_Wth + (size_t)(bn + crow1) * GK + kof + cch1 * 8;
            const __nv_bfloat16* bl = g_Wtl + (size_t)(bn + crow1) * GK + kof + cch1 * 8;
            uint32_t d = st + crow1 * 80 + cch1 * 16;
            cp16(d, ah); cp16(d + TILE_B, al); cp16(d + 2 * TILE_B, bh); cp16(d + 3 * TILE_B, bl);
        }
        asm volatile("cp.async.commit_group;" ::: "memory");
    };

    stage_copy(0, 0);

    for (int kt = 0; kt < 32; kt++) {
        if (kt + 1 < 32) {
            stage_copy((kt + 1) & 1, kt + 1);
            asm volatile("cp.async.wait_group 1;" ::: "memory");
        } else {
            asm volatile("cp.async.wait_group 0;" ::: "memory");
        }
        __syncthreads();

        uint32_t st = smbase + (kt & 1) * STAGE_B;
        #pragma unroll
        for (int ks = 0; ks < 2; ks++) {
            const int kof = ks * 16;
            uint32_t ah[4][4], al[4][4];
            #pragma unroll
            for (int mi = 0; mi < 4; mi++) {
                uint32_t addr = st + (wm + mi * 16 + (lane & 15)) * 80
                              + (kof + (lane >> 4) * 8) * 2;
                ldsm4(ah[mi], addr);
                ldsm4(al[mi], addr + TILE_B);
            }
            #pragma unroll
            for (int nip = 0; nip < 2; nip++) {
                uint32_t baddr = st + 2 * TILE_B
                               + (wn + nip * 16 + (lane & 7) + ((lane >> 4) << 3)) * 80
                               + (kof + ((lane >> 3) & 1) * 8) * 2;
                uint32_t bh[4], bl[4];
                ldsm4(bh, baddr);
                ldsm4(bl, baddr + TILE_B);
                #pragma unroll
                for (int mi = 0; mi < 4; mi++) {
                    mma16816(acc[mi][2 * nip],     ah[mi], bh[0], bh[1]);
                    mma16816(acc[mi][2 * nip],     ah[mi], bl[0], bl[1]);
                    mma16816(acc[mi][2 * nip],     al[mi], bh[0], bh[1]);
                    mma16816(acc[mi][2 * nip + 1], ah[mi], bh[2], bh[3]);
                    mma16816(acc[mi][2 * nip + 1], ah[mi], bl[2], bl[3]);
                    mma16816(acc[mi][2 * nip + 1], al[mi], bh[2], bh[3]);
                }
            }
        }
        __syncthreads();
    }

    // epilogue: bias + store
    #pragma unroll
    for (int mi = 0; mi < 4; mi++) {
        int row = bm + wm + mi * 16 + gid;
        #pragma unroll
        for (int ni = 0; ni < 4; ni++) {
            int col = bn + wn + ni * 8 + tig * 2;
            float b0 = bias[col], b1 = bias[col + 1];
            float2 r01 = make_float2(acc[mi][ni][0] + b0, acc[mi][ni][1] + b1);
            float2 r23 = make_float2(acc[mi][ni][2] + b0, acc[mi][ni][3] + b1);
            *reinterpret_cast<float2*>(&C[(size_t)row * GN + col])       = r01;
            *reinterpret_cast<float2*>(&C[(size_t)(row + 8) * GN + col]) = r23;
        }
    }
}

// ---------------------------------------------------------------------------
// Per-position attention (unchanged from round 4)
// ---------------------------------------------------------------------------
__global__ __launch_bounds__(256) void attn_kernel(
    const float* __restrict__ SW, float* AT)
{
    const int p = blockIdx.x;
    const int b = p >> 12;
    const int s = p & 4095;
    const int tid = threadIdx.x;

    __shared__ __align__(16) float qs[16][65];
    __shared__ __align__(16) float ks_[16][65];
    __shared__ __align__(16) float vs[16][64];
    __shared__ float qn2[16], kn2[16];
    __shared__ float att[16][16];

    const size_t base = (size_t)p * 1024;
    {
        int e = tid * 4;
        int r = e >> 6, d = e & 63;
        float4 qv = *reinterpret_cast<const float4*>(g_Q + base + e);
        float4 kv = *reinterpret_cast<const float4*>(g_K + base + e);
        float4 vv = *reinterpret_cast<const float4*>(g_V + base + e);
        qs[r][d] = qv.x; qs[r][d + 1] = qv.y; qs[r][d + 2] = qv.z; qs[r][d + 3] = qv.w;
        ks_[r][d] = kv.x; ks_[r][d + 1] = kv.y; ks_[r][d + 2] = kv.z; ks_[r][d + 3] = kv.w;
        *reinterpret_cast<float4*>(&vs[r][d]) = vv;
    }
    float w0, w1, w2;
    {
        float s0 = SW[0], s1 = SW[1], s2 = SW[2];
        float mx = fmaxf(s0, fmaxf(s1, s2));
        float e0 = expf(s0 - mx), e1 = expf(s1 - mx), e2 = expf(s2 - mx);
        float inv = 1.f / (e0 + e1 + e2);
        w0 = e0 * inv; w1 = e1 * inv; w2 = e2 * inv;
    }
    __syncthreads();

    if (tid < 32) {
        int r = tid & 15;
        const float* src = (tid < 16) ? qs[r] : ks_[r];
        float ssum = 0.f;
        #pragma unroll 8
        for (int d = 0; d < 64; d++) ssum += src[d] * src[d];
        if (tid < 16) qn2[r] = ssum; else kn2[r] = ssum;
    }
    __syncthreads();

    {
        int i = tid >> 4, j = tid & 15;
        float qk = 0.f;
        #pragma unroll 8
        for (int d = 0; d < 64; d++) qk += qs[i][d] * ks_[j][d];
        float sq = qn2[i], sk = kn2[j];
        float dots  = qk * 0.125f;
        float denom = fmaxf(sqrtf(sq) * sqrtf(sk), 1e-8f);
        float cosv  = qk / denom;
        float d2    = fmaxf(sq + sk - 2.f * qk, 0.f);
        float dist  = -sqrtf(d2);
        float sc = w0 * dots + w1 * cosv + w2 * dist;

        float mx = sc;
        #pragma unroll
        for (int o = 8; o; o >>= 1) mx = fmaxf(mx, __shfl_xor_sync(0xffffffffu, mx, o, 16));
        float e = expf(sc - mx);
        float sm = e;
        #pragma unroll
        for (int o = 8; o; o >>= 1) sm += __shfl_xor_sync(0xffffffffu, sm, o, 16);
        float a = e / sm;
        att[i][j] = a;
        if (AT) AT[(size_t)p * 256 + tid] = a;
    }
    __syncthreads();

    {
        int i = tid >> 4, d0 = (tid & 15) * 4;
        float4 o = make_float4(0.f, 0.f, 0.f, 0.f);
        #pragma unroll
        for (int j = 0; j < 16; j++) {
            float a = att[i][j];
            float4 v4 = *reinterpret_cast<const float4*>(&vs[j][d0]);
            o.x += a * v4.x; o.y += a * v4.y; o.z += a * v4.z; o.w += a * v4.w;
        }
        size_t xidx = (size_t)b * 4194304 + (size_t)i * 262144 + (size_t)s * 64 + d0;
        *reinterpret_cast<float4*>(&g_X[xidx]) = o;
    }
}

// ---------------------------------------------------------------------------
// kernel_launch
// ---------------------------------------------------------------------------
extern "C" void kernel_launch(void* const* d_in, const int* in_sizes, int n_in,
                              void* d_out, int out_size) {
    (void)in_sizes; (void)n_in;
    const float* query = (const float*)d_in[0];
    const float* key   = (const float*)d_in[1];
    const float* value = (const float*)d_in[2];
    const float* Wq = (const float*)d_in[3];
    const float* bq = (const float*)d_in[4];
    const float* Wk = (const float*)d_in[5];
    const float* bk = (const float*)d_in[6];
    const float* Wv = (const float*)d_in[7];
    const float* bv = (const float*)d_in[8];
    const float* Wo = (const float*)d_in[9];
    const float* bo = (const float*)d_in[10];
    const float* sw = (const float*)d_in[11];
    float* out = (float*)d_out;

    static bool attr_set = false;
    if (!attr_set) {
        cudaFuncSetAttribute(gemm_tc_kernel,
                             cudaFuncAttributeMaxDynamicSharedMemorySize, GSMEM);
        attr_set = true;
    }

    dim3 ggrid(GN / 128, GM / 128);      // (8, 128)
    dim3 wgrid(GN / 32, GK / 32);        // (32, 32)
    const int sgrid = (GM * GK) / (256 * 4);  // 16384

    // Q projection
    split_a_kernel<<<sgrid, 256>>>(query);
    split_wt_kernel<<<wgrid, 256>>>(Wq);
    gemm_tc_kernel<<<ggrid, 256, GSMEM>>>(nullptr, 1, bq);
    // K projection
    split_a_kernel<<<sgrid, 256>>>(key);
    split_wt_kernel<<<wgrid, 256>>>(Wk);
    gemm_tc_kernel<<<ggrid, 256, GSMEM>>>(nullptr, 2, bk);
    // V projection
    split_a_kernel<<<sgrid, 256>>>(value);
    split_wt_kernel<<<wgrid, 256>>>(Wv);
    gemm_tc_kernel<<<ggrid, 256, GSMEM>>>(nullptr, 3, bv);

    // Attention (writes g_X; probs to d_out tail iff tuple output)
    float* attn_dst = (out_size >= MAIN_OUT_ELEMS + ATT_ELEMS) ? (out + MAIN_OUT_ELEMS)
                                                               : nullptr;
    attn_kernel<<<NPOS, 256>>>(sw, attn_dst);

    // Output projection
    split_a_kernel<<<sgrid, 256>>>(nullptr);   // reads g_X
    split_wt_kernel<<<wgrid, 256>>>(Wo);
    gemm_tc_kernel<<<ggrid, 256, GSMEM>>>(out, 0, bo);
}